// round 16
// baseline (speedup 1.0000x reference)
#include <cuda_runtime.h>
#include <cuda_fp16.h>
#include <cstdint>

// ---------------------------------------------------------------------------
constexpr int BATCH = 4;
constexpr int SEQ   = 2048;
constexpr int HID   = 1024;
constexpr int NHEAD = 16;
constexpr int HDIM  = 64;
constexpr int MROWS = BATCH * SEQ;                       // 8192
constexpr long long OUT_ELEMS = (long long)MROWS * HID;  // 8,388,608

// GEMM tiles: 32-col chunks, rows padded to 40 fp16 (80 B = 16B-aligned rows)
constexpr int LDT = 40;
constexpr int TILE_B = 128 * LDT * 2;     // 10240
constexpr int GBUF   = 4 * TILE_B;        // qkv: Ah,Al,Bh,Bl = 40960
constexpr int SMEM_G = 2 * GBUF;          // 81920 (2-stage, 2 CTAs/SM)
constexpr int GBUF2  = 3 * TILE_B;        // out: Ah,Bh,Bl = 30720
constexpr int SMEM_G2 = 3 * GBUF2;        // 92160 (3-stage single-sync)

// Attention tiles: 64-col rows padded to 72 fp16 (144 B = 16B-aligned rows)
constexpr int LDA_B  = 144;
constexpr int QTILE  = 128 * LDA_B;       // 18432
constexpr int KT64   = 64 * LDA_B;        // 9216
constexpr int KT128  = 128 * LDA_B;       // 18432 (pass-A K tile)
constexpr int OQH = 0;
constexpr int OQL = QTILE;                // Q region: 0..36864, dead after prologue
constexpr int OSA = 2 * QTILE;            // 36864: pass A ring, 3 slots x KT128
constexpr int BGRP = 4 * KT64;            // 36864: pass B group (Kh,Kl,Vh,Vl)
constexpr int SMEM_ATTN = 3 * BGRP;       // 110592 (covers OSA + 3*KT128 = 92160)

// ---------------------------------------------------------------------------
// Prepped fp16 hi/lo operands
// ---------------------------------------------------------------------------
__device__ __half g_xh[MROWS * HID], g_xl[MROWS * HID];
__device__ __half g_wh[4 * HID * HID], g_wl[4 * HID * HID];
__device__ __half g_qh[64 * SEQ * HDIM], g_ql[64 * SEQ * HDIM];
__device__ __half g_kh[64 * SEQ * HDIM], g_kl[64 * SEQ * HDIM];
__device__ __half g_vh[64 * SEQ * HDIM], g_vl[64 * SEQ * HDIM];
__device__ __half g_ch[MROWS * HID];     // ctx: hi only

// ---------------------------------------------------------------------------
__device__ __forceinline__ uint32_t smem_u32(const void* p) {
    uint32_t a;
    asm("{ .reg .u64 t; cvta.to.shared.u64 t, %1; cvt.u32.u64 %0, t; }"
        : "=r"(a) : "l"(p));
    return a;
}

__device__ __forceinline__ void ldsm4(uint32_t* r, uint32_t a) {
    asm volatile("ldmatrix.sync.aligned.m8n8.x4.shared.b16 {%0,%1,%2,%3}, [%4];"
                 : "=r"(r[0]), "=r"(r[1]), "=r"(r[2]), "=r"(r[3]) : "r"(a));
}
__device__ __forceinline__ void ldsm4t(uint32_t* r, uint32_t a) {
    asm volatile("ldmatrix.sync.aligned.m8n8.x4.trans.shared.b16 {%0,%1,%2,%3}, [%4];"
                 : "=r"(r[0]), "=r"(r[1]), "=r"(r[2]), "=r"(r[3]) : "r"(a));
}

#define MMA_F16(d, a, b0, b1)                                               \
    asm volatile(                                                           \
        "mma.sync.aligned.m16n8k16.row.col.f32.f16.f16.f32 "                \
        "{%0,%1,%2,%3}, {%4,%5,%6,%7}, {%8,%9}, {%0,%1,%2,%3};"             \
        : "+f"((d)[0]), "+f"((d)[1]), "+f"((d)[2]), "+f"((d)[3])            \
        : "r"((a)[0]), "r"((a)[1]), "r"((a)[2]), "r"((a)[3]),               \
          "r"(b0), "r"(b1))

__device__ __forceinline__ void cp16(uint32_t dst, const void* src) {
    asm volatile("cp.async.cg.shared.global [%0], [%1], 16;" :: "r"(dst), "l"(src));
}
#define CP_COMMIT asm volatile("cp.async.commit_group;" ::: "memory")
#define CP_WAIT1  asm volatile("cp.async.wait_group 1;" ::: "memory")
#define CP_WAIT0  asm volatile("cp.async.wait_group 0;" ::: "memory")

__device__ __forceinline__ uint32_t pack2(float x, float y) {
    __half2 h = __floats2half2_rn(x, y);
    return *(uint32_t*)&h;
}

__device__ __forceinline__ void pack_hl(float x, float y, uint32_t& h, uint32_t& l) {
    __half hx = __float2half_rn(x);
    __half hy = __float2half_rn(y);
    __half lx = __float2half_rn(x - __half2float(hx));
    __half ly = __float2half_rn(y - __half2float(hy));
    h = ((uint32_t)__half_as_ushort(hy) << 16) | __half_as_ushort(hx);
    l = ((uint32_t)__half_as_ushort(ly) << 16) | __half_as_ushort(lx);
}

// ---------------------------------------------------------------------------
// prep: split X and the 4 weight matrices into fp16 hi/lo once.
// ---------------------------------------------------------------------------
__global__ void __launch_bounds__(256) prep(
    const float* __restrict__ X,  const float* __restrict__ Wq,
    const float* __restrict__ Wk, const float* __restrict__ Wv,
    const float* __restrict__ Wo)
{
    const long long NX = (long long)MROWS * HID;
    long long i = (long long)blockIdx.x * 256 + threadIdx.x;
    float v; __half *dh, *dl; long long o;
    if (i < NX) {
        v = X[i]; dh = g_xh; dl = g_xl; o = i;
    } else {
        long long j = i - NX;
        int w = (int)(j >> 20);
        long long r = j & 1048575;
        if (w == 0) v = Wq[r]; else if (w == 1) v = Wk[r];
        else if (w == 2) v = Wv[r]; else v = Wo[r];
        dh = g_wh; dl = g_wl; o = j;
    }
    __half hb = __float2half_rn(v);
    dh[o] = hb;
    dl[o] = __float2half_rn(v - __half2float(hb));
}

// ---------------------------------------------------------------------------
// 3-term split-fp16 warp MMA over one 32-wide K chunk (qkv).
// ---------------------------------------------------------------------------
template <int MF, int NF>
__device__ __forceinline__ void mma_chunk3(float (&acc)[MF][NF][4],
                                           uint32_t aHi, uint32_t aLo,
                                           uint32_t bHi, uint32_t bLo,
                                           int mbase, int nbase, int lane)
{
    const int r16 = lane & 15;
    const int koL = (lane >> 4) * 16;
#pragma unroll
    for (int ks = 0; ks < 2; ks++) {
        const int kb = ks * 32 + koL;
        uint32_t FA[4 * MF], FB[2 * NF], FC[2 * NF];
#pragma unroll
        for (int mf = 0; mf < MF; mf++)
            ldsm4(&FA[4 * mf], aHi + (mbase + mf * 16 + r16) * (LDT * 2) + kb);
#pragma unroll
        for (int nb = 0; nb < NF / 2; nb++)
            ldsm4(&FB[4 * nb], bHi + (nbase + nb * 16 + r16) * (LDT * 2) + kb);
#pragma unroll
        for (int mf = 0; mf < MF; mf++)
#pragma unroll
            for (int nf = 0; nf < NF; nf++)
                MMA_F16(acc[mf][nf], &FA[4 * mf],
                        FB[4 * (nf >> 1) + (nf & 1)], FB[4 * (nf >> 1) + 2 + (nf & 1)]);
#pragma unroll
        for (int nb = 0; nb < NF / 2; nb++)
            ldsm4(&FC[4 * nb], bLo + (nbase + nb * 16 + r16) * (LDT * 2) + kb);
#pragma unroll
        for (int mf = 0; mf < MF; mf++)
#pragma unroll
            for (int nf = 0; nf < NF; nf++)
                MMA_F16(acc[mf][nf], &FA[4 * mf],
                        FC[4 * (nf >> 1) + (nf & 1)], FC[4 * (nf >> 1) + 2 + (nf & 1)]);
#pragma unroll
        for (int mf = 0; mf < MF; mf++)
            ldsm4(&FA[4 * mf], aLo + (mbase + mf * 16 + r16) * (LDT * 2) + kb);
#pragma unroll
        for (int mf = 0; mf < MF; mf++)
#pragma unroll
            for (int nf = 0; nf < NF; nf++)
                MMA_F16(acc[mf][nf], &FA[4 * mf],
                        FB[4 * (nf >> 1) + (nf & 1)], FB[4 * (nf >> 1) + 2 + (nf & 1)]);
    }
}

// 2-term variant: A hi only, B hi+lo (out projection).
template <int MF, int NF>
__device__ __forceinline__ void mma_chunk2(float (&acc)[MF][NF][4],
                                           uint32_t aHi,
                                           uint32_t bHi, uint32_t bLo,
                                           int mbase, int nbase, int lane)
{
    const int r16 = lane & 15;
    const int koL = (lane >> 4) * 16;
#pragma unroll
    for (int ks = 0; ks < 2; ks++) {
        const int kb = ks * 32 + koL;
        uint32_t FA[4 * MF], FB[2 * NF];
#pragma unroll
        for (int mf = 0; mf < MF; mf++)
            ldsm4(&FA[4 * mf], aHi + (mbase + mf * 16 + r16) * (LDT * 2) + kb);
#pragma unroll
        for (int nb = 0; nb < NF / 2; nb++)
            ldsm4(&FB[4 * nb], bHi + (nbase + nb * 16 + r16) * (LDT * 2) + kb);
#pragma unroll
        for (int mf = 0; mf < MF; mf++)
#pragma unroll
            for (int nf = 0; nf < NF; nf++)
                MMA_F16(acc[mf][nf], &FA[4 * mf],
                        FB[4 * (nf >> 1) + (nf & 1)], FB[4 * (nf >> 1) + 2 + (nf & 1)]);
#pragma unroll
        for (int nb = 0; nb < NF / 2; nb++)
            ldsm4(&FB[4 * nb], bLo + (nbase + nb * 16 + r16) * (LDT * 2) + kb);
#pragma unroll
        for (int mf = 0; mf < MF; mf++)
#pragma unroll
            for (int nf = 0; nf < NF; nf++)
                MMA_F16(acc[mf][nf], &FA[4 * mf],
                        FB[4 * (nf >> 1) + (nf & 1)], FB[4 * (nf >> 1) + 2 + (nf & 1)]);
    }
}

// cp.async a 128x32 fp16 tile (ld = HID) into LDT=40 smem (256 thr)
__device__ __forceinline__ void cp_tile32(const __half* __restrict__ src,
                                          uint32_t dst, int tid) {
#pragma unroll
    for (int i = 0; i < 2; i++) {
        int id = tid + i * 256;
        int r = id >> 2, c = id & 3;
        cp16(dst + r * (LDT * 2) + c * 16, src + (long long)r * HID + c * 8);
    }
}

// ---------------------------------------------------------------------------
// QKV projection (3-term, 2-stage, SINGLE sync: cp issued after the barrier
// targets the buffer all warps finished reading before it).
// grid(8, 64, 3), 256 thr.
// ---------------------------------------------------------------------------
__global__ void __launch_bounds__(256, 2) mm_qkv(
    const float* __restrict__ bq, const float* __restrict__ bk,
    const float* __restrict__ bv)
{
    extern __shared__ char sm[];
    const int z = blockIdx.z;
    const float* bias = (z == 0) ? bq : (z == 1) ? bk : bv;
    __half* dsth = (z == 0) ? g_qh : (z == 1) ? g_kh : g_vh;
    __half* dstl = (z == 0) ? g_ql : (z == 1) ? g_kl : g_vl;

    const int tid = threadIdx.x, lane = tid & 31, wid = tid >> 5;
    const int mw = wid >> 2, nw = wid & 3;
    const int m0 = blockIdx.y * 128, n0 = blockIdx.x * 128;
    const __half* Ah = g_xh + (long long)m0 * HID;
    const __half* Al = g_xl + (long long)m0 * HID;
    const __half* Bh = g_wh + (long long)z * HID * HID + (long long)n0 * HID;
    const __half* Bl = g_wl + (long long)z * HID * HID + (long long)n0 * HID;
    const uint32_t s0 = smem_u32(sm);

    float acc[4][4][4];
#pragma unroll
    for (int i = 0; i < 4; i++)
#pragma unroll
        for (int j = 0; j < 4; j++)
#pragma unroll
            for (int q = 0; q < 4; q++) acc[i][j][q] = 0.f;

    cp_tile32(Ah, s0 + 0 * TILE_B, tid);
    cp_tile32(Al, s0 + 1 * TILE_B, tid);
    cp_tile32(Bh, s0 + 2 * TILE_B, tid);
    cp_tile32(Bl, s0 + 3 * TILE_B, tid);
    CP_COMMIT;

    for (int c = 0; c < 32; c++) {
        CP_WAIT0;            // group c complete (issued last iteration)
        __syncthreads();     // all warps done reading the other buffer
        if (c + 1 < 32) {    // prefetch into the buffer just released
            uint32_t nb = s0 + ((c + 1) & 1) * GBUF;
            cp_tile32(Ah + (c + 1) * 32, nb + 0 * TILE_B, tid);
            cp_tile32(Al + (c + 1) * 32, nb + 1 * TILE_B, tid);
            cp_tile32(Bh + (c + 1) * 32, nb + 2 * TILE_B, tid);
            cp_tile32(Bl + (c + 1) * 32, nb + 3 * TILE_B, tid);
            CP_COMMIT;
        }
        uint32_t buf = s0 + (c & 1) * GBUF;
        mma_chunk3<4, 4>(acc, buf, buf + TILE_B, buf + 2 * TILE_B, buf + 3 * TILE_B,
                         mw * 64, nw * 32, lane);
    }

    const int g = lane >> 2, tig = lane & 3;
#pragma unroll
    for (int mf = 0; mf < 4; mf++) {
#pragma unroll
        for (int half = 0; half < 2; half++) {
            const int m = m0 + mw * 64 + mf * 16 + g + half * 8;
            const int b = m >> 11, s = m & 2047;
#pragma unroll
            for (int nf = 0; nf < 4; nf++) {
                const int n = n0 + nw * 32 + nf * 8 + tig * 2;
                const int h = n >> 6, d = n & 63;
                float vx = acc[mf][nf][half * 2 + 0] + bias[n + 0];
                float vy = acc[mf][nf][half * 2 + 1] + bias[n + 1];
                uint32_t hw, lw;
                pack_hl(vx, vy, hw, lw);
                long long idx = ((long long)(b * NHEAD + h) * SEQ + s) * HDIM + d;
                *(uint32_t*)(dsth + idx) = hw;
                *(uint32_t*)(dstl + idx) = lw;
            }
        }
    }
}

// ---------------------------------------------------------------------------
// Attention, 256 threads, 128-row Q, 2 CTAs/SM, single-sync rings.
// Pass A: 128-row K tiles (16 iters).  Pass B: 64-row KV groups (32 iters).
// grid(16, 64).
// ---------------------------------------------------------------------------
__device__ __forceinline__ void cp_kv64(const __half* __restrict__ src,
                                        uint32_t dst, int tid) {
#pragma unroll
    for (int i = 0; i < 2; i++) {
        int id = tid + i * 256;
        int r = id >> 3, c = id & 7;
        cp16(dst + r * LDA_B + c * 16, src + (long long)r * HDIM + c * 8);
    }
}
__device__ __forceinline__ void cp_t128(const __half* __restrict__ src,
                                        uint32_t dst, int tid) {
#pragma unroll
    for (int i = 0; i < 4; i++) {
        int id = tid + i * 256;
        int r = id >> 3, c = id & 7;
        cp16(dst + r * LDA_B + c * 16, src + (long long)r * HDIM + c * 8);
    }
}

// 3-term S tile: Qh*Kh + Qh*Kl + Ql*Kh   (pass B)
__device__ __forceinline__ void s_tile3(float* acc,
                                        const uint32_t* FQh, const uint32_t* FQl,
                                        uint32_t kh, uint32_t kl, int nfp, int lane)
{
    const int r16 = lane & 15;
    const int koL = (lane >> 4) * 16;
    const uint32_t rowoff = (uint32_t)(nfp * 16 + r16) * LDA_B;
#pragma unroll
    for (int ks = 0; ks < 4; ks++) {
        uint32_t FBh[4], FBl[4];
        ldsm4(FBh, kh + rowoff + ks * 32 + koL);
        ldsm4(FBl, kl + rowoff + ks * 32 + koL);
        MMA_F16(acc,     &FQh[4 * ks], FBh[0], FBh[2]);
        MMA_F16(acc + 4, &FQh[4 * ks], FBh[1], FBh[3]);
        MMA_F16(acc,     &FQh[4 * ks], FBl[0], FBl[2]);
        MMA_F16(acc + 4, &FQh[4 * ks], FBl[1], FBl[3]);
        MMA_F16(acc,     &FQl[4 * ks], FBh[0], FBh[2]);
        MMA_F16(acc + 4, &FQl[4 * ks], FBh[1], FBh[3]);
    }
}

// 2-term S tile for pass A sums: Qh*Kh + Ql*Kh
__device__ __forceinline__ void s_tile2(float* acc,
                                        const uint32_t* FQh, const uint32_t* FQl,
                                        uint32_t kh, int nfp, int lane)
{
    const int r16 = lane & 15;
    const int koL = (lane >> 4) * 16;
    const uint32_t rowoff = (uint32_t)(nfp * 16 + r16) * LDA_B;
#pragma unroll
    for (int ks = 0; ks < 4; ks++) {
        uint32_t FBh[4];
        ldsm4(FBh, kh + rowoff + ks * 32 + koL);
        MMA_F16(acc,     &FQh[4 * ks], FBh[0], FBh[2]);
        MMA_F16(acc + 4, &FQh[4 * ks], FBh[1], FBh[3]);
        MMA_F16(acc,     &FQl[4 * ks], FBh[0], FBh[2]);
        MMA_F16(acc + 4, &FQl[4 * ks], FBh[1], FBh[3]);
    }
}

__global__ void __launch_bounds__(256, 2) attn(float* __restrict__ probs)
{
    extern __shared__ char sm[];
    const int tid = threadIdx.x, lane = tid & 31, w = tid >> 5;   // w: 0..7
    const int g = lane >> 2, tig = lane & 3;
    const int bh = blockIdx.y;
    const int m0 = blockIdx.x * 128;
    const uint32_t s0 = smem_u32(sm);

    const __half* Qh = g_qh + ((long long)bh * SEQ + m0) * HDIM;
    const __half* Ql = g_ql + ((long long)bh * SEQ + m0) * HDIM;
    const __half* Kh = g_kh + (long long)bh * SEQ * HDIM;
    const __half* Kl = g_kl + (long long)bh * SEQ * HDIM;
    const __half* Vh = g_vh + (long long)bh * SEQ * HDIM;
    const __half* Vl = g_vl + (long long)bh * SEQ * HDIM;
    float* C = probs + (long long)bh * SEQ * SEQ;

    // prologue: Q (group), K0 (128 rows) into pass-A slot 0 (group)
    cp_t128(Qh, s0 + OQH, tid);
    cp_t128(Ql, s0 + OQL, tid);
    CP_COMMIT;
    cp_t128(Kh, s0 + OSA, tid);
    CP_COMMIT;
    CP_WAIT1;           // Q done (K0 may be in flight)
    __syncthreads();

    uint32_t FQh[16], FQl[16];
    {
        const uint32_t arow = (uint32_t)(w * 16 + (lane & 15)) * LDA_B;
        const uint32_t koL = (lane >> 4) * 16;
#pragma unroll
        for (int ks = 0; ks < 4; ks++) {
            ldsm4(&FQh[4 * ks], s0 + OQH + arow + ks * 32 + koL);
            ldsm4(&FQl[4 * ks], s0 + OQL + arow + ks * 32 + koL);
        }
    }
    // Q smem region is dead from here on (fragments live in registers)

    // ------------- pass A: 3-slot 128-row Kh ring, single sync/iter -------
    float sum0 = 0.f, sum1 = 0.f;
    for (int j = 0; j < 16; j++) {
        if (j + 1 < 16)
            cp_t128(Kh + (long long)(j + 1) * 128 * HDIM,
                    s0 + OSA + ((j + 1) % 3) * KT128, tid);
        CP_COMMIT;
        CP_WAIT1;
        __syncthreads();
        const uint32_t kh = s0 + OSA + (j % 3) * KT128;
#pragma unroll
        for (int nfp = 0; nfp < 8; nfp++) {
            float acc[8] = {0.f, 0.f, 0.f, 0.f, 0.f, 0.f, 0.f, 0.f};
            s_tile2(acc, FQh, FQl, kh, nfp, lane);
            sum0 += __expf(acc[0]) + __expf(acc[1]) + __expf(acc[4]) + __expf(acc[5]);
            sum1 += __expf(acc[2]) + __expf(acc[3]) + __expf(acc[6]) + __expf(acc[7]);
        }
    }
#pragma unroll
    for (int o = 1; o <= 2; o <<= 1) {
        sum0 += __shfl_xor_sync(0xffffffffu, sum0, o);
        sum1 += __shfl_xor_sync(0xffffffffu, sum1, o);
    }
    const float ri0 = 1.0f / sum0;
    const float ri1 = 1.0f / sum1;

    // ---------------- pass B: 3-group KV ring (reuses Q region) -----------
    float ctx[8][4];
#pragma unroll
    for (int i = 0; i < 8; i++)
#pragma unroll
        for (int q = 0; q < 4; q++) ctx[i][q] = 0.f;

    // group 0 lives at offset 0 (= dead Q region): safe to fill while
    // stragglers finish pass A (they only touch OSA and registers).
    {
        uint32_t sl = s0;
        cp_kv64(Kh, sl, tid);
        cp_kv64(Kl, sl + KT64, tid);
        cp_kv64(Vh, sl + 2 * KT64, tid);
        cp_kv64(Vl, sl + 3 * KT64, tid);
        CP_COMMIT;
    }
    __syncthreads();   // all warps past pass A before group 1 overwrites OSA

    const long long rowg = m0 + w * 16 + g;
    const uint32_t vlanerow = (uint32_t)((lane & 7) + ((lane >> 4) & 1) * 8) * LDA_B
                              + ((lane >> 3) & 1) * 16;

    for (int j = 0; j < 32; j++) {
        if (j + 1 < 32) {
            uint32_t sl = s0 + ((j + 1) % 3) * BGRP;
            cp_kv64(Kh + (long long)(j + 1) * 64 * HDIM, sl, tid);
            cp_kv64(Kl + (long long)(j + 1) * 64 * HDIM, sl + KT64, tid);
            cp_kv64(Vh + (long long)(j + 1) * 64 * HDIM, sl + 2 * KT64, tid);
            cp_kv64(Vl + (long long)(j + 1) * 64 * HDIM, sl + 3 * KT64, tid);
        }
        CP_COMMIT;
        CP_WAIT1;
        __syncthreads();
        const uint32_t kh = s0 + (j % 3) * BGRP;
        const uint32_t kl = kh + KT64;
        const uint32_t vh = kh + 2 * KT64;
        const uint32_t vl = kh + 3 * KT64;

#pragma unroll
        for (int nfp = 0; nfp < 4; nfp++) {
            float acc[8] = {0.f, 0.f, 0.f, 0.f, 0.f, 0.f, 0.f, 0.f};
            s_tile3(acc, FQh, FQl, kh, kl, nfp, lane);
            float pE0 = __expf(acc[0]) * ri0, pE1 = __expf(acc[1]) * ri0;
            float pE2 = __expf(acc[2]) * ri1, pE3 = __expf(acc[3]) * ri1;
            float pO0 = __expf(acc[4]) * ri0, pO1 = __expf(acc[5]) * ri0;
            float pO2 = __expf(acc[6]) * ri1, pO3 = __expf(acc[7]) * ri1;
            float* Cr = C + rowg * SEQ + j * 64 + nfp * 16 + tig * 2;
            __stcs((float2*)Cr,                 make_float2(pE0, pE1));
            __stcs((float2*)(Cr + 8),           make_float2(pO0, pO1));
            __stcs((float2*)(Cr + 8 * SEQ),     make_float2(pE2, pE3));
            __stcs((float2*)(Cr + 8 * SEQ + 8), make_float2(pO2, pO3));
            uint32_t PAh[4];
            PAh[0] = pack2(pE0, pE1);
            PAh[1] = pack2(pE2, pE3);
            PAh[2] = pack2(pO0, pO1);
            PAh[3] = pack2(pO2, pO3);
            const uint32_t vbase = (uint32_t)(nfp * 16) * LDA_B + vlanerow;
#pragma unroll
            for (int gd = 0; gd < 4; gd++) {
                uint32_t FVh[4], FVl[4];
                ldsm4t(FVh, vh + vbase + gd * 32);
                ldsm4t(FVl, vl + vbase + gd * 32);
                MMA_F16(ctx[2 * gd + 0], PAh, FVh[0], FVh[2]);
                MMA_F16(ctx[2 * gd + 0], PAh, FVl[0], FVl[2]);
                MMA_F16(ctx[2 * gd + 1], PAh, FVh[1], FVh[3]);
                MMA_F16(ctx[2 * gd + 1], PAh, FVl[1], FVl[3]);
            }
        }
    }

    // ctx epilogue -> fp16 (hi only) [b][s][h*64+d]
    const int b = bh >> 4, h = bh & 15;
    const int s = m0 + w * 16 + g;
    const long long base = ((long long)(b * SEQ + s)) * HID + h * HDIM;
#pragma unroll
    for (int dnf = 0; dnf < 8; dnf++) {
        const int d = dnf * 8 + tig * 2;
        *(uint32_t*)(g_ch + base + d) = pack2(ctx[dnf][0], ctx[dnf][1]);
        *(uint32_t*)(g_ch + base + 8LL * HID + d) = pack2(ctx[dnf][2], ctx[dnf][3]);
    }
}

// ---------------------------------------------------------------------------
// Output projection + residual (2-term, 3-stage single-sync).  grid(8, 64).
// ---------------------------------------------------------------------------
__global__ void __launch_bounds__(256, 2) mm_out(
    const float* __restrict__ bo, const float* __restrict__ hidden,
    float* __restrict__ out)
{
    extern __shared__ char sm[];
    const int tid = threadIdx.x, lane = tid & 31, wid = tid >> 5;
    const int mw = wid >> 2, nw = wid & 3;
    const int m0 = blockIdx.y * 128, n0 = blockIdx.x * 128;
    const __half* Ah = g_ch + (long long)m0 * HID;
    const __half* Bh = g_wh + 3LL * HID * HID + (long long)n0 * HID;
    const __half* Bl = g_wl + 3LL * HID * HID + (long long)n0 * HID;
    const uint32_t s0 = smem_u32(sm);

    float acc[4][4][4];
#pragma unroll
    for (int i = 0; i < 4; i++)
#pragma unroll
        for (int j = 0; j < 4; j++)
#pragma unroll
            for (int q = 0; q < 4; q++) acc[i][j][q] = 0.f;

    cp_tile32(Ah, s0 + 0 * TILE_B, tid);
    cp_tile32(Bh, s0 + 1 * TILE_B, tid);
    cp_tile32(Bl, s0 + 2 * TILE_B, tid);
    CP_COMMIT;

    for (int c = 0; c < 32; c++) {
        if (c + 1 < 32) {
            uint32_t nb = s0 + ((c + 1) % 3) * GBUF2;
            cp_tile32(Ah + (c + 1) * 32, nb + 0 * TILE_B, tid);
            cp_tile32(Bh + (c + 1) * 32, nb + 1 * TILE_B, tid);
            cp_tile32(Bl + (c + 1) * 32, nb + 2 * TILE_B, tid);
        }
        CP_COMMIT;
        CP_WAIT1;
        __syncthreads();
        uint32_t buf = s0 + (c % 3) * GBUF2;
        mma_chunk2<4, 4>(acc, buf, buf + TILE_B, buf + 2 * TILE_B,
                         mw * 64, nw * 32, lane);
        // single-sync: 3-stage ring, distance-1 prefetch is race-free
    }

    const int g = lane >> 2, tig = lane & 3;
#pragma unroll
    for (int mf = 0; mf < 4; mf++) {
#pragma unroll
        for (int half = 0; half < 2; half++) {
            const long long m = m0 + mw * 64 + mf * 16 + g + half * 8;
#pragma unroll
            for (int nf = 0; nf < 4; nf++) {
                const int n = n0 + nw * 32 + nf * 8 + tig * 2;
                float2 hd = *(const float2*)(hidden + m * HID + n);
                float2 st;
                st.x = acc[mf][nf][half * 2 + 0] + bo[n + 0] + hd.x;
                st.y = acc[mf][nf][half * 2 + 1] + bo[n + 1] + hd.y;
                *(float2*)(out + m * HID + n) = st;
            }
        }
    }
}

// ---------------------------------------------------------------------------
extern "C" void kernel_launch(void* const* d_in, const int* in_sizes, int n_in,
                              void* d_out, int out_size)
{
    const float* X  = (const float*)d_in[0];
    const float* Wq = (const float*)d_in[1];
    const float* bq = (const float*)d_in[2];
    const float* Wk = (const float*)d_in[3];
    const float* bk = (const float*)d_in[4];
    const float* Wv = (const float*)d_in[5];
    const float* bv = (const float*)d_in[6];
    const float* Wo = (const float*)d_in[7];
    const float* bo = (const float*)d_in[8];

    float* out   = (float*)d_out;
    float* probs = out + OUT_ELEMS;

    cudaFuncSetAttribute(mm_qkv, cudaFuncAttributeMaxDynamicSharedMemorySize, SMEM_G);
    cudaFuncSetAttribute(mm_out, cudaFuncAttributeMaxDynamicSharedMemorySize, SMEM_G2);
    cudaFuncSetAttribute(attn,   cudaFuncAttributeMaxDynamicSharedMemorySize, SMEM_ATTN);

    const long long NPREP = (long long)MROWS * HID + 4LL * HID * HID;
    prep<<<(unsigned)((NPREP + 255) / 256), 256>>>(X, Wq, Wk, Wv, Wo);
    mm_qkv<<<dim3(HID / 128, MROWS / 128, 3), 256, SMEM_G>>>(bq, bk, bv);
    attn<<<dim3(SEQ / 128, BATCH * NHEAD), 256, SMEM_ATTN>>>(probs);
    mm_out<<<dim3(HID / 128, MROWS / 128), 256, SMEM_G2>>>(bo, X, out);
}